// round 1
// baseline (speedup 1.0000x reference)
#include <cuda_runtime.h>

#define FULLMASK 0xffffffffu

// scratch (allocation-free contract: __device__ globals)
__device__ float g_s[16384];        // softmax logits, one per (b, c)
__device__ float g_hfsel[512*128];  // hf row at agent_id per b
__device__ float g_red[2];          // softmax max, sumexp

__device__ __forceinline__ float wredsum(float v){
  #pragma unroll
  for(int o=16;o;o>>=1) v += __shfl_xor_sync(FULLMASK,v,o);
  return v;
}

// ---- shared memory layout (floats) ----
#define OFF_W2   0        // 16384  linh_w[0]
#define OFF_W3   16384    // 16384  linh_w[1]
#define OFF_W1   32768    // 4096   lin1_w (later reused: b2a, fc2b)
#define OFF_BASE 36864    // 4096   base[r][h]
#define OFF_HACC 40960    // 4096   h accumulator [c][h]
#define OFF_AT   45056    // 8320   activation tile transposed [k][65]
#define OFF_EL   53376    // 1024   e values of active edges
#define OFF_LN1G 54400    // 128
#define OFF_LN1B 54528    // 128
#define OFF_LHB  54656    // 256    linh_b
#define OFF_LHG  54912    // 256    lnh_g
#define OFF_LHBB 55168    // 256    lnh_b
#define OFF_CL   55424    // 1024   (c<<5)|r of active edges (int)
#define OFF_MISC 56448    // 32     scan temporaries
#define SMEM_FLOATS 56480
#define SMEM_BYTES (SMEM_FLOATS*4)

__global__ __launch_bounds__(256,1)
void gnn_k1(const float* __restrict__ node_obs, const float* __restrict__ adj,
            const int* __restrict__ agent_id, const float* __restrict__ emb,
            const float* __restrict__ lin1_w, const float* __restrict__ lin1_b,
            const float* __restrict__ ln1_g, const float* __restrict__ ln1_b,
            const float* __restrict__ linh_w, const float* __restrict__ linh_b,
            const float* __restrict__ lnh_g, const float* __restrict__ lnh_b,
            const float* __restrict__ fc2a_w, const float* __restrict__ fc2a_b,
            const float* __restrict__ fc2b_w, const float* __restrict__ fc2b_b)
{
  extern __shared__ float sm[];
  float* sW2  = sm+OFF_W2;
  float* sW3  = sm+OFF_W3;
  float* sW1  = sm+OFF_W1;
  float* base = sm+OFF_BASE;
  float* hacc = sm+OFF_HACC;
  float* sAt  = sm+OFF_AT;
  float* elist= sm+OFF_EL;
  int*   clist=(int*)(sm+OFF_CL);
  float* sxj  = sAt;               // alias: used only before tile loop
  int*   swsum=(int*)(sm+OFF_MISC);
  int*   swoff=swsum+8;
  int*   snact=swoff+8;

  const int b=blockIdx.x, t=threadIdx.x, lane=t&31, w=t>>5;

  // ---- cooperative loads into smem ----
  {
    const float4* s2=(const float4*)(linh_w);
    const float4* s3=(const float4*)(linh_w+16384);
    float4* d2=(float4*)sW2; float4* d3=(float4*)sW3;
    for(int i=t;i<4096;i+=256){ d2[i]=s2[i]; d3[i]=s3[i]; }
    const float4* s1=(const float4*)lin1_w; float4* d1=(float4*)sW1;
    for(int i=t;i<1024;i+=256) d1[i]=s1[i];
  }
  if(t<128){ sm[OFF_LN1G+t]=ln1_g[t]; sm[OFF_LN1B+t]=ln1_b[t]; }
  { int i=t; if(i<256){ sm[OFF_LHB+i]=linh_b[i]; sm[OFF_LHG+i]=lnh_g[i]; sm[OFF_LHBB+i]=lnh_b[i]; } }
  for(int i=t;i<4096;i+=256) hacc[i]=0.f;

  // xj per r: 15 feats + 16-dim entity embedding
  if(t<32){
    const int r=t;
    const float* no = node_obs + (size_t)b*512 + r*16;
    #pragma unroll
    for(int k=0;k<15;k++) sxj[r*32+k]=no[k];
    int ent=(int)no[15];
    #pragma unroll
    for(int j=0;j<16;j++) sxj[r*32+15+j]=emb[ent*16+j];
    sxj[r*32+31]=0.f;
  }
  __syncthreads();

  // ---- base[r][h] = xj[r] @ W1[0:31] + b1  (layer-1 shared part) ----
  {
    const int h=t&127, r0=t>>7;
    for(int r=r0;r<32;r+=2){
      float acc=lin1_b[h];
      #pragma unroll
      for(int k=0;k<31;k++) acc += sxj[r*32+k]*sW1[k*128+h];
      base[r*128+h]=acc;
    }
  }

  // ---- edge compaction (c-major order), block scan ----
  float ev4[4]; int rc4[4]; int act4[4]; int cnt=0;
  #pragma unroll
  for(int q=0;q<4;q++){
    int idx=t*4+q; int c=idx>>5; int r=idx&31;
    float v=adj[(size_t)b*1024 + r*32 + c];
    int a=(v>0.f)&&(v<1.0f);
    act4[q]=a; ev4[q]=v; rc4[q]=(c<<5)|r; cnt+=a;
  }
  int x=cnt;
  #pragma unroll
  for(int o=1;o<32;o<<=1){int y=__shfl_up_sync(FULLMASK,x,o); if(lane>=o)x+=y;}
  if(lane==31) swsum[w]=x;
  __syncthreads();
  if(t==0){ int run=0;
    #pragma unroll
    for(int i=0;i<8;i++){ swoff[i]=run; run+=swsum[i]; }
    snact[0]=run;
  }
  __syncthreads();
  { int pos=swoff[w]+x-cnt;
    #pragma unroll
    for(int q=0;q<4;q++){ if(act4[q]){ clist[pos]=rc4[q]; elist[pos]=ev4[q]; pos++; } }
  }
  const int nact=snact[0];
  __syncthreads();   // base + edge list ready; sxj (alias of sAt) now free

  const float4 w1l = *(const float4*)&sW1[31*128+lane*4];
  const float4 g1  = *(const float4*)&sm[OFF_LN1G+lane*4];
  const float4 b1v = *(const float4*)&sm[OFF_LN1B+lane*4];

  const int nt=(nact+63)/64;
  for(int T=0;T<nt;T++){
    const int tb=T*64;
    const int colb=w*8;
    // ---- layer 1: pre = base[r] + e*W1[31], relu, LN -> sAt (transposed) ----
    #pragma unroll
    for(int jj=0;jj<8;jj++){
      int iloc=colb+jj, gi=tb+iloc;
      int r=0; float e=0.f;
      if(gi<nact){ int rc=clist[gi]; r=rc&31; e=elist[gi]; }
      float4 bs=*(const float4*)&base[r*128+lane*4];
      float vx=fmaxf(fmaf(e,w1l.x,bs.x),0.f);
      float vy=fmaxf(fmaf(e,w1l.y,bs.y),0.f);
      float vz=fmaxf(fmaf(e,w1l.z,bs.z),0.f);
      float vw=fmaxf(fmaf(e,w1l.w,bs.w),0.f);
      float s1=wredsum(vx+vy+vz+vw);
      float s2=wredsum(vx*vx+vy*vy+vz*vz+vw*vw);
      float mu=s1*(1.f/128.f);
      float inv=rsqrtf(s2*(1.f/128.f)-mu*mu+1e-5f);
      sAt[(lane*4+0)*65+iloc]=(vx-mu)*inv*g1.x+b1v.x;
      sAt[(lane*4+1)*65+iloc]=(vy-mu)*inv*g1.y+b1v.y;
      sAt[(lane*4+2)*65+iloc]=(vz-mu)*inv*g1.z+b1v.z;
      sAt[(lane*4+3)*65+iloc]=(vw-mu)*inv*g1.w+b1v.w;
    }
    __syncwarp();
    // ---- two hidden layers: 128x128 GEMM per 64-row tile, warp = 8 rows ----
    #pragma unroll
    for(int l=0;l<2;l++){
      const float* Wl = l? sW3 : sW2;
      float4 bl=*(const float4*)&sm[OFF_LHB+l*128+lane*4];
      float acc[8][4];
      #pragma unroll
      for(int jj=0;jj<8;jj++){acc[jj][0]=bl.x;acc[jj][1]=bl.y;acc[jj][2]=bl.z;acc[jj][3]=bl.w;}
      #pragma unroll 4
      for(int k=0;k<128;k++){
        float4 wv=*(const float4*)&Wl[k*128+lane*4];
        const float* arow=&sAt[k*65+colb];
        #pragma unroll
        for(int jj=0;jj<8;jj++){
          float a=arow[jj];
          acc[jj][0]=fmaf(a,wv.x,acc[jj][0]);
          acc[jj][1]=fmaf(a,wv.y,acc[jj][1]);
          acc[jj][2]=fmaf(a,wv.z,acc[jj][2]);
          acc[jj][3]=fmaf(a,wv.w,acc[jj][3]);
        }
      }
      float4 gl =*(const float4*)&sm[OFF_LHG +l*128+lane*4];
      float4 bbl=*(const float4*)&sm[OFF_LHBB+l*128+lane*4];
      #pragma unroll
      for(int jj=0;jj<8;jj++){
        float vx=fmaxf(acc[jj][0],0.f), vy=fmaxf(acc[jj][1],0.f);
        float vz=fmaxf(acc[jj][2],0.f), vw=fmaxf(acc[jj][3],0.f);
        float s1=wredsum(vx+vy+vz+vw);
        float s2=wredsum(vx*vx+vy*vy+vz*vz+vw*vw);
        float mu=s1*(1.f/128.f);
        float inv=rsqrtf(s2*(1.f/128.f)-mu*mu+1e-5f);
        int iloc=colb+jj;
        sAt[(lane*4+0)*65+iloc]=(vx-mu)*inv*gl.x+bbl.x;
        sAt[(lane*4+1)*65+iloc]=(vy-mu)*inv*gl.y+bbl.y;
        sAt[(lane*4+2)*65+iloc]=(vz-mu)*inv*gl.z+bbl.z;
        sAt[(lane*4+3)*65+iloc]=(vw-mu)*inv*gl.w+bbl.w;
      }
      __syncwarp();
    }
    // ---- deterministic aggregation: h[c][h] += m[edge][h] (mask==1) ----
    __syncthreads();
    if(t<128){
      for(int i=0;i<64;i++){
        int gi=tb+i;
        if(gi>=nact) break;
        int c=clist[gi]>>5;
        hacc[c*128+t]+=sAt[t*65+i];
      }
    }
    __syncthreads();
  }

  // ---- stage B: s[b,c] = relu(h @ fc2a + b2a) @ fc2b + b2b  (all 32 rows) ----
  {
    const float4* s2=(const float4*)fc2a_w; float4* d2=(float4*)sW2;
    for(int i=t;i<4096;i+=256) d2[i]=s2[i];
    if(t<128){ sW1[t]=fc2a_b[t]; sW1[128+t]=fc2b_w[t]; }
  }
  __syncthreads();
  {
    float4 b2=*(const float4*)&sW1[lane*4];
    float4 f2=*(const float4*)&sW1[128+lane*4];
    float acc[4][4];
    #pragma unroll
    for(int cc=0;cc<4;cc++){acc[cc][0]=b2.x;acc[cc][1]=b2.y;acc[cc][2]=b2.z;acc[cc][3]=b2.w;}
    const int c0=w*4;
    #pragma unroll 4
    for(int k=0;k<128;k++){
      float4 wv=*(const float4*)&sW2[k*128+lane*4];
      #pragma unroll
      for(int cc=0;cc<4;cc++){
        float a=hacc[(c0+cc)*128+k];
        acc[cc][0]=fmaf(a,wv.x,acc[cc][0]);
        acc[cc][1]=fmaf(a,wv.y,acc[cc][1]);
        acc[cc][2]=fmaf(a,wv.z,acc[cc][2]);
        acc[cc][3]=fmaf(a,wv.w,acc[cc][3]);
      }
    }
    float b2b=fc2b_b[0];
    #pragma unroll
    for(int cc=0;cc<4;cc++){
      float p=fmaxf(acc[cc][0],0.f)*f2.x+fmaxf(acc[cc][1],0.f)*f2.y
             +fmaxf(acc[cc][2],0.f)*f2.z+fmaxf(acc[cc][3],0.f)*f2.w;
      p=wredsum(p);
      if(lane==0) g_s[b*32+c0+cc]=p+b2b;
    }
  }
  // stash the hf row this batch actually uses
  if(t<128){
    int ag=agent_id[b];
    g_hfsel[b*128+t]=hacc[ag*128+t];
  }
}

// ---- global softmax reduction over 16384 logits ----
__global__ void gnn_k2(){
  __shared__ float sw[8];
  int t=threadIdx.x, lane=t&31, w=t>>5;
  float m=-3.4e38f;
  for(int i=t;i<16384;i+=256) m=fmaxf(m,g_s[i]);
  #pragma unroll
  for(int o=16;o;o>>=1) m=fmaxf(m,__shfl_xor_sync(FULLMASK,m,o));
  if(lane==0) sw[w]=m;
  __syncthreads();
  float M=sw[0];
  #pragma unroll
  for(int i=1;i<8;i++) M=fmaxf(M,sw[i]);
  float acc=0.f;
  for(int i=t;i<16384;i+=256) acc+=expf(g_s[i]-M);
  acc=wredsum(acc);
  __syncthreads();
  if(lane==0) sw[w]=acc;
  __syncthreads();
  if(t==0){
    float S=0.f;
    #pragma unroll
    for(int i=0;i<8;i++) S+=sw[i];
    g_red[0]=M; g_red[1]=S;
  }
}

// ---- per-b head on the single selected row ----
__global__ __launch_bounds__(128)
void gnn_k3(const float* __restrict__ fc3_w, const float* __restrict__ fc3_b,
            const float* __restrict__ ln3_g, const float* __restrict__ ln3_b,
            const float* __restrict__ fc4_w, const float* __restrict__ fc4_b,
            const float* __restrict__ ln4_g, const float* __restrict__ ln4_b,
            const int* __restrict__ agent_id, float* __restrict__ out)
{
  __shared__ float shf[128], sy[128], sred[8];
  int b=blockIdx.x, t=threadIdx.x, lane=t&31, w=t>>5;
  shf[t]=g_hfsel[b*128+t];
  __syncthreads();
  float acc=fc3_b[t];
  #pragma unroll 4
  for(int k=0;k<128;k++) acc=fmaf(shf[k],fc3_w[k*128+t],acc);
  float v=fmaxf(acc,0.f);
  float s1=wredsum(v), s2=wredsum(v*v);
  if(lane==0){sred[w]=s1; sred[4+w]=s2;}
  __syncthreads();
  s1=sred[0]+sred[1]+sred[2]+sred[3];
  s2=sred[4]+sred[5]+sred[6]+sred[7];
  float mu=s1*(1.f/128.f);
  float inv=rsqrtf(s2*(1.f/128.f)-mu*mu+1e-5f);
  float vn=(v-mu)*inv*ln3_g[t]+ln3_b[t];
  int ag=agent_id[b];
  float alpha=expf(g_s[b*32+ag]-g_red[0])/g_red[1];
  sy[t]=alpha*vn;
  __syncthreads();
  acc=fc4_b[t];
  #pragma unroll 4
  for(int k=0;k<128;k++) acc=fmaf(sy[k],fc4_w[k*128+t],acc);
  v=fmaxf(acc,0.f);
  s1=wredsum(v); s2=wredsum(v*v);
  __syncthreads();
  if(lane==0){sred[w]=s1; sred[4+w]=s2;}
  __syncthreads();
  s1=sred[0]+sred[1]+sred[2]+sred[3];
  s2=sred[4]+sred[5]+sred[6]+sred[7];
  mu=s1*(1.f/128.f);
  inv=rsqrtf(s2*(1.f/128.f)-mu*mu+1e-5f);
  out[b*128+t]=(v-mu)*inv*ln4_g[t]+ln4_b[t];
}

extern "C" void kernel_launch(void* const* d_in, const int* in_sizes, int n_in,
                              void* d_out, int out_size)
{
  const float* node_obs=(const float*)d_in[0];
  const float* adj     =(const float*)d_in[1];
  const int*   agent_id=(const int*)  d_in[2];
  const float* emb     =(const float*)d_in[3];
  const float* lin1_w  =(const float*)d_in[4];
  const float* lin1_b  =(const float*)d_in[5];
  const float* ln1_g   =(const float*)d_in[6];
  const float* ln1_b   =(const float*)d_in[7];
  const float* linh_w  =(const float*)d_in[8];
  const float* linh_b  =(const float*)d_in[9];
  const float* lnh_g   =(const float*)d_in[10];
  const float* lnh_b   =(const float*)d_in[11];
  const float* fc2a_w  =(const float*)d_in[12];
  const float* fc2a_b  =(const float*)d_in[13];
  const float* fc2b_w  =(const float*)d_in[14];
  const float* fc2b_b  =(const float*)d_in[15];
  const float* fc3_w   =(const float*)d_in[16];
  const float* fc3_b   =(const float*)d_in[17];
  const float* ln3_g   =(const float*)d_in[18];
  const float* ln3_b   =(const float*)d_in[19];
  const float* fc4_w   =(const float*)d_in[20];
  const float* fc4_b   =(const float*)d_in[21];
  const float* ln4_g   =(const float*)d_in[22];
  const float* ln4_b   =(const float*)d_in[23];

  cudaFuncSetAttribute(gnn_k1, cudaFuncAttributeMaxDynamicSharedMemorySize, SMEM_BYTES);

  gnn_k1<<<512,256,SMEM_BYTES>>>(node_obs,adj,agent_id,emb,
                                 lin1_w,lin1_b,ln1_g,ln1_b,
                                 linh_w,linh_b,lnh_g,lnh_b,
                                 fc2a_w,fc2a_b,fc2b_w,fc2b_b);
  gnn_k2<<<1,256>>>();
  gnn_k3<<<512,128>>>(fc3_w,fc3_b,ln3_g,ln3_b,fc4_w,fc4_b,ln4_g,ln4_b,
                      agent_id,(float*)d_out);
}